// round 10
// baseline (speedup 1.0000x reference)
#include <cuda_runtime.h>
#include <cstdint>

#define DM 2048
#define DS 16
#define SEQ 4096
#define NB 4
#define NROWS (NB*SEQ)
#define CHL 32                 // chunk body length
#define CHW 20                 // warmup steps (contraction ~0.08^20 ~ 1e-22)
#define NCHUNK (SEQ/CHL)       // 128 chunks per batch

// ---- scratch (static device arrays: no allocation allowed) ----
__device__ float  g_u[NROWS*DS + 1024]; // padded: prefetch overrun safe
__device__ float2 g_murs[NROWS];
__device__ float  g_hist2[NROWS*32];    // stride 32; lanes 16-31 write junk cols

__device__ __forceinline__ float tanh_fast(float x){
    float y;
    asm("tanh.approx.f32 %0, %1;" : "=f"(y) : "f"(x));
    return y;
}

// ---------------------------------------------------------------------------
// kernA: 512 threads (16 warps -> 4 warps/SMSP to fill latency stalls).
//   Each thread owns 4 d-elements (bg tile 16x4). Per row: dots + 2-round
//   butterfly -> 128 partials/value in double-buffered SMEM -> ONE barrier
//   -> warp 0 sums (MLP-covered LDS) + writes u/murs; others run ahead.
// ---------------------------------------------------------------------------
__global__ __launch_bounds__(512, 1)
void kernA(const float* __restrict__ x,
           const float* __restrict__ B,
           const float* __restrict__ gamma,
           const float* __restrict__ beta){
    const int tid  = threadIdx.x;
    const int lane = tid & 31, warp = tid >> 5;   // 16 warps
    const int d0   = tid * 4;
    const unsigned FULL = 0xFFFFFFFFu;

    __shared__ float spart[2][128][20]; // [buf][warp*8+lane(<8)][value(18)]
    __shared__ float scb[32];           // cB[16], bB[16]

    float gg[4], bt[4];
    {
        float4 t0 = *(const float4*)(gamma + d0);
        gg[0]=t0.x; gg[1]=t0.y; gg[2]=t0.z; gg[3]=t0.w;
        float4 u0 = *(const float4*)(beta + d0);
        bt[0]=u0.x; bt[1]=u0.y; bt[2]=u0.z; bt[3]=u0.w;
    }

    float bg[16][4];                   // gamma-folded B, register-resident
    {
        float pc[16], pb[16];
        #pragma unroll
        for (int s = 0; s < 16; s++){
            float4 b0 = *(const float4*)(B + s*DM + d0);
            float br[4] = {b0.x,b0.y,b0.z,b0.w};
            float c = 0.f, b2 = 0.f;
            #pragma unroll
            for (int k = 0; k < 4; k++){
                bg[s][k] = br[k] * gg[k];
                c  += bg[s][k];
                b2  = fmaf(bt[k], br[k], b2);
            }
            pc[s] = c; pb[s] = b2;
        }
        #pragma unroll
        for (int off = 16; off > 0; off >>= 1){
            #pragma unroll
            for (int s = 0; s < 16; s++){
                pc[s] += __shfl_xor_sync(FULL, pc[s], off);
                pb[s] += __shfl_xor_sync(FULL, pb[s], off);
            }
        }
        if (lane == 0){
            #pragma unroll
            for (int s = 0; s < 16; s++){
                spart[0][warp][s]      = pc[s];   // rows 0-15: cB partials
                spart[0][16 + warp][s] = pb[s];   // rows 16-31: bB partials
            }
        }
        __syncthreads();
        if (tid < 32){
            int i = tid & 15, grp = tid >> 4;     // grp 0: cB, grp 1: bB
            float t = spart[0][grp*16 + 0][i];
            #pragma unroll
            for (int w = 1; w < 16; w++) t += spart[0][grp*16 + w][i];
            scb[tid] = t;
        }
        __syncthreads();
    }
    float cBl = scb[lane & 15];
    float bBl = scb[16 + (lane & 15)];
    __syncthreads();

    int row = blockIdx.x;
    const int stride = gridDim.x;
    int pbuf = 0;

    auto ldx4 = [&](int r){
        int rc = r < NROWS ? r : 0;
        return *(const float4*)(x + (size_t)rc*DM + d0);
    };
    float4 xa = ldx4(row);
    float4 xc = ldx4(row + stride);

    for (; row < NROWS; row += stride){
        float xs[4] = {xa.x, xa.y, xa.z, xa.w};
        xa = xc;
        xc = ldx4(row + 2*stride);

        float p[18];
        {
            float s1 = 0.f, s2 = 0.f;
            #pragma unroll
            for (int k = 0; k < 4; k++){ s1 += xs[k]; s2 = fmaf(xs[k], xs[k], s2); }
            p[16] = s1; p[17] = s2;
        }
        #pragma unroll
        for (int s = 0; s < 16; s++){
            float acc = xs[0]*bg[s][0];
            #pragma unroll
            for (int k = 1; k < 4; k++) acc = fmaf(xs[k], bg[s][k], acc);
            p[s] = acc;
        }
        // 2 butterfly rounds -> lanes 0-7 hold sums of {l, l+8, l+16, l+24}
        #pragma unroll
        for (int i = 0; i < 18; i++) p[i] += __shfl_xor_sync(FULL, p[i], 16);
        #pragma unroll
        for (int i = 0; i < 18; i++) p[i] += __shfl_xor_sync(FULL, p[i], 8);
        if (lane < 8){
            float* dst = spart[pbuf][warp*8 + lane];
            *(float4*)(dst)      = make_float4(p[0],  p[1],  p[2],  p[3]);
            *(float4*)(dst + 4)  = make_float4(p[4],  p[5],  p[6],  p[7]);
            *(float4*)(dst + 8)  = make_float4(p[8],  p[9],  p[10], p[11]);
            *(float4*)(dst + 12) = make_float4(p[12], p[13], p[14], p[15]);
            *(float2*)(dst + 16) = make_float2(p[16], p[17]);
        }
        __syncthreads();               // the ONLY barrier per row
        if (warp == 0){                // warp 0 tail; warps 1-15 run ahead
            float t0 = 0.f, t1 = 0.f, t2 = 0.f, t3 = 0.f;
            #pragma unroll
            for (int j = 0; j < 128; j += 4){
                t0 += spart[pbuf][j    ][lane];
                t1 += spart[pbuf][j + 1][lane];
                t2 += spart[pbuf][j + 2][lane];
                t3 += spart[pbuf][j + 3][lane];
            }
            float t = (t0 + t1) + (t2 + t3);   // lanes 18-31: junk
            float s1 = __shfl_sync(FULL, t, 16);
            float s2 = __shfl_sync(FULL, t, 17);
            float mu  = s1 * (1.0f/DM);
            float var = s2 * (1.0f/DM) - mu*mu;
            float rs  = rsqrtf(var + 1e-5f);
            if (lane < 16){
                g_u[row*DS + lane] = fmaf(-mu, cBl, t) * rs + bBl;
            } else if (lane == 16){
                g_murs[row] = make_float2(mu, rs);
            }
        }
        pbuf ^= 1;                     // double buffer: tail never races STS
    }
}

// ---------------------------------------------------------------------------
// kernScan: chunked-parallel exact scan (unchanged).
// ---------------------------------------------------------------------------
__global__ __launch_bounds__(32, 1)
void kernScan(const float* __restrict__ A){
    const int chunk = blockIdx.x;
    const int b     = chunk / NCHUNK;
    const int c     = chunk % NCHUNK;
    const int t0    = c * CHL;
    const int start = (c == 0) ? 0 : (t0 - CHW);
    const int steps = t0 + CHL - start;
    const int lane  = threadIdx.x;

    float a[16];
    #pragma unroll
    for (int j = 0; j < 16; j++) a[j] = A[j*DS + (lane & 15)];

    const float* ub = g_u     + (size_t)b * SEQ * DS + (size_t)start * DS;
    float*       hb = g_hist2 + (size_t)(b * SEQ + start) * 32;

    __shared__ float sh[2][32];
    sh[0][lane] = 0.f;
    __syncthreads();

    float uq[4];
    #pragma unroll
    for (int k = 0; k < 4; k++) uq[k] = ub[k*DS + lane];

    const int body0 = t0 - start;
    for (int s = 0; s < steps; s += 4){
        #pragma unroll
        for (int k = 0; k < 4; k++){
            const int i = s + k;
            const int p = i & 1;
            float uc = uq[k];
            uq[k] = ub[(i + 4)*DS + lane];

            float4 H0 = *(const float4*)&sh[p][0];
            float4 H1 = *(const float4*)&sh[p][4];
            float4 H2 = *(const float4*)&sh[p][8];
            float4 H3 = *(const float4*)&sh[p][12];

            float a0 = fmaf(H0.x, a[0], uc);
            float a1 = H0.y * a[1];
            float a2 = H0.z * a[2];
            float a3 = H0.w * a[3];
            float a4 = H1.x * a[4];
            float a5 = H1.y * a[5];
            float a6 = H1.z * a[6];
            float a7 = H1.w * a[7];
            a0 = fmaf(H2.x, a[8],  a0);
            a1 = fmaf(H2.y, a[9],  a1);
            a2 = fmaf(H2.z, a[10], a2);
            a3 = fmaf(H2.w, a[11], a3);
            a4 = fmaf(H3.x, a[12], a4);
            a5 = fmaf(H3.y, a[13], a5);
            a6 = fmaf(H3.z, a[14], a6);
            a7 = fmaf(H3.w, a[15], a7);
            float v = ((a0 + a1) + (a2 + a3)) + ((a4 + a5) + (a6 + a7));
            float h = tanh_fast(v);

            sh[p ^ 1][lane] = h;
            __syncthreads();

            if (i >= body0) hb[i*32 + lane] = h;
        }
    }
}

// ---------------------------------------------------------------------------
// kernC: R8 shape (measured best): half-DM split, 2 blocks/SM, float4 I/O,
//        2-row pairwise unroll + 2-pair x prefetch.
// ---------------------------------------------------------------------------
__global__ __launch_bounds__(256, 2)
void kernC(const float* __restrict__ x,
           const float* __restrict__ Cm,
           const float* __restrict__ Dp,
           const float* __restrict__ gamma,
           const float* __restrict__ beta,
           float* __restrict__ out){
    const int tid  = threadIdx.x;
    const int half = blockIdx.x & 1;
    const int d0   = half * (DM/2) + tid * 4;

    float e[4], f[4];
    {
        float4 dp = *(const float4*)(Dp    + d0);
        float4 g  = *(const float4*)(gamma + d0);
        float4 btv= *(const float4*)(beta  + d0);
        float dv[4] = {dp.x,dp.y,dp.z,dp.w};
        float gv[4] = {g.x,g.y,g.z,g.w};
        float bv[4] = {btv.x,btv.y,btv.z,btv.w};
        #pragma unroll
        for (int k = 0; k < 4; k++){
            float cc = 1.0f + dv[k];
            e[k] = cc * gv[k];
            f[k] = cc * bv[k];
        }
    }
    float cr[16][4];
    #pragma unroll
    for (int s = 0; s < 16; s++){
        float4 c0 = *(const float4*)(Cm + s*DM + d0);
        cr[s][0]=c0.x; cr[s][1]=c0.y; cr[s][2]=c0.z; cr[s][3]=c0.w;
    }

    const int base = blockIdx.x >> 1;             // 0..147
    auto ldx = [&](int r){                        // clamp-indexed (branchless)
        int rc = r < NROWS ? r : NROWS-1;
        return *(const float4*)(x + (size_t)rc*DM + d0);
    };
    float4 x0 = ldx(base);
    float4 x1 = ldx(base + 148);
    float4 p0 = ldx(base + 296);
    float4 p1 = ldx(base + 444);

    for (int r = base; r < NROWS; r += 296){
        float4 c0 = x0, c1 = x1;
        x0 = p0; x1 = p1;
        p0 = ldx(r + 592);
        p1 = ldx(r + 740);

        int rB  = r + 148;
        int rBc = rB < NROWS ? rB : NROWS-1;

        float2 mrA = g_murs[r];
        float2 mrB = g_murs[rBc];
        const float4* hpA = (const float4*)(g_hist2 + (size_t)r*32);
        const float4* hpB = (const float4*)(g_hist2 + (size_t)rBc*32);
        float4 hA0 = hpA[0], hA1 = hpA[1], hA2 = hpA[2], hA3 = hpA[3];
        float4 hB0 = hpB[0], hB1 = hpB[1], hB2 = hpB[2], hB3 = hpB[3];
        float hvA[16] = {hA0.x,hA0.y,hA0.z,hA0.w, hA1.x,hA1.y,hA1.z,hA1.w,
                         hA2.x,hA2.y,hA2.z,hA2.w, hA3.x,hA3.y,hA3.z,hA3.w};
        float hvB[16] = {hB0.x,hB0.y,hB0.z,hB0.w, hB1.x,hB1.y,hB1.z,hB1.w,
                         hB2.x,hB2.y,hB2.z,hB2.w, hB3.x,hB3.y,hB3.z,hB3.w};

        float xsA[4] = {c0.x, c0.y, c0.z, c0.w};
        float xsB[4] = {c1.x, c1.y, c1.z, c1.w};
        float oA[4], oB[4];
        #pragma unroll
        for (int k = 0; k < 4; k++){
            float xcA = (xsA[k] - mrA.x) * mrA.y;
            float xcB = (xsB[k] - mrB.x) * mrB.y;
            float aA  = fmaf(e[k], xcA, f[k]);
            float aB  = fmaf(e[k], xcB, f[k]);
            #pragma unroll
            for (int s = 0; s < 16; s++){
                aA = fmaf(hvA[s], cr[s][k], aA);
                aB = fmaf(hvB[s], cr[s][k], aB);
            }
            oA[k] = aA; oB[k] = aB;
        }
        *(float4*)(out + (size_t)r*DM + d0) = make_float4(oA[0], oA[1], oA[2], oA[3]);
        if (rB < NROWS)
            *(float4*)(out + (size_t)rB*DM + d0) = make_float4(oB[0], oB[1], oB[2], oB[3]);
    }
}

// ---------------------------------------------------------------------------
extern "C" void kernel_launch(void* const* d_in, const int* in_sizes, int n_in,
                              void* d_out, int out_size){
    const float* x     = (const float*)d_in[0];
    const float* A     = (const float*)d_in[1];
    const float* B     = (const float*)d_in[2];
    const float* C     = (const float*)d_in[3];
    const float* Dp    = (const float*)d_in[4];
    const float* gamma = (const float*)d_in[5];
    const float* beta  = (const float*)d_in[6];
    float* out = (float*)d_out;

    kernA<<<148, 512>>>(x, B, gamma, beta);
    kernScan<<<NB*NCHUNK, 32>>>(A);
    kernC<<<296, 256>>>(x, C, Dp, gamma, beta, out);
}

// round 11
// speedup vs baseline: 1.3683x; 1.3683x over previous
#include <cuda_runtime.h>
#include <cstdint>

#define DM 2048
#define DS 16
#define SEQ 4096
#define NB 4
#define NROWS (NB*SEQ)
#define CHL 32                 // chunk body length
#define CHW 20                 // warmup steps (contraction ~0.08^20 ~ 1e-22)
#define NCHUNK (SEQ/CHL)       // 128 chunks per batch

// ---- scratch (static device arrays: no allocation allowed) ----
__device__ float  g_u[NROWS*DS + 1024]; // padded: prefetch overrun safe
__device__ float2 g_murs[NROWS];
__device__ float  g_hist2[NROWS*32];    // stride 32; lanes 16-31 write junk cols

__device__ __forceinline__ float tanh_fast(float x){
    float y;
    asm("tanh.approx.f32 %0, %1;" : "=f"(y) : "f"(x));
    return y;
}

// ---------------------------------------------------------------------------
// kernA: 256 threads, 8 d-elems/thread, B reg-resident. Software-pipelined
//   reduction: row r's dot FFMAs (fma pipe, high ILP) interleave with row
//   (r-stride)'s butterfly SHFLs (MIO pipe, latency 26) -> SHFL latency is
//   hidden under FMA issue. One barrier per row; warp-0 tail overlapped.
// ---------------------------------------------------------------------------
__global__ __launch_bounds__(256, 1)
void kernA(const float* __restrict__ x,
           const float* __restrict__ B,
           const float* __restrict__ gamma,
           const float* __restrict__ beta){
    const int tid  = threadIdx.x;
    const int lane = tid & 31, warp = tid >> 5;
    const int d0   = tid * 8;
    const unsigned FULL = 0xFFFFFFFFu;

    __shared__ float spart[2][64][20];  // [buf][warp*8+lane(<8)][value(18)]
    __shared__ float scb[32];           // cB[16], bB[16]

    float gg[8], bt[8];
    {
        float4 t0 = *(const float4*)(gamma + d0);
        float4 t1 = *(const float4*)(gamma + d0 + 4);
        gg[0]=t0.x; gg[1]=t0.y; gg[2]=t0.z; gg[3]=t0.w;
        gg[4]=t1.x; gg[5]=t1.y; gg[6]=t1.z; gg[7]=t1.w;
        float4 u0 = *(const float4*)(beta + d0);
        float4 u1 = *(const float4*)(beta + d0 + 4);
        bt[0]=u0.x; bt[1]=u0.y; bt[2]=u0.z; bt[3]=u0.w;
        bt[4]=u1.x; bt[5]=u1.y; bt[6]=u1.z; bt[7]=u1.w;
    }

    float bg[16][8];                   // gamma-folded B, register-resident
    {
        float pc[16], pb[16];
        #pragma unroll
        for (int s = 0; s < 16; s++){
            float4 b0 = *(const float4*)(B + s*DM + d0);
            float4 b1 = *(const float4*)(B + s*DM + d0 + 4);
            float br[8] = {b0.x,b0.y,b0.z,b0.w,b1.x,b1.y,b1.z,b1.w};
            float c = 0.f, b2 = 0.f;
            #pragma unroll
            for (int k = 0; k < 8; k++){
                bg[s][k] = br[k] * gg[k];
                c  += bg[s][k];
                b2  = fmaf(bt[k], br[k], b2);
            }
            pc[s] = c; pb[s] = b2;
        }
        #pragma unroll
        for (int off = 16; off > 0; off >>= 1){
            #pragma unroll
            for (int s = 0; s < 16; s++){
                pc[s] += __shfl_xor_sync(FULL, pc[s], off);
                pb[s] += __shfl_xor_sync(FULL, pb[s], off);
            }
        }
        if (lane == 0){
            #pragma unroll
            for (int s = 0; s < 16; s++){
                spart[0][warp][s]     = pc[s];
                spart[0][8 + warp][s] = pb[s];
            }
        }
        __syncthreads();
        if (tid < 32){
            int i = tid & 15, grp = tid >> 4;
            float t = spart[0][grp*8 + 0][i];
            #pragma unroll
            for (int w = 1; w < 8; w++) t += spart[0][grp*8 + w][i];
            scb[tid] = t;
        }
        __syncthreads();
    }
    float cBl = scb[lane & 15];
    float bBl = scb[16 + (lane & 15)];
    __syncthreads();

    const int stride = gridDim.x;
    int pbuf = 0;
    float pv[18];                      // previous row's un-reduced partials
    int   prow = -1;                   // row pv belongs to

    auto ldx4 = [&](int r, int off){
        int rc = r < NROWS ? r : 0;
        return *(const float4*)(x + (size_t)rc*DM + d0 + off);
    };
    int row = blockIdx.x;
    float4 xa = ldx4(row, 0),        xb = ldx4(row, 4);
    float4 xc = ldx4(row+stride, 0), xd = ldx4(row+stride, 4);

    for (; row < NROWS; row += stride){
        float xs[8] = {xa.x, xa.y, xa.z, xa.w, xb.x, xb.y, xb.z, xb.w};
        xa = xc; xb = xd;
        {
            int nr = row + 2*stride;
            xc = ldx4(nr, 0); xd = ldx4(nr, 4);
        }

        // ---- current row's dots (fma pipe, high ILP) ----
        float p[18];
        {
            float s1 = 0.f, s2 = 0.f;
            #pragma unroll
            for (int k = 0; k < 8; k++){ s1 += xs[k]; s2 = fmaf(xs[k], xs[k], s2); }
            p[16] = s1; p[17] = s2;
        }
        #pragma unroll
        for (int s = 0; s < 16; s++){
            float acc = xs[0]*bg[s][0];
            #pragma unroll
            for (int k = 1; k < 8; k++) acc = fmaf(xs[k], bg[s][k], acc);
            p[s] = acc;
        }

        // ---- previous row's butterfly (MIO pipe) — interleaves with dots ----
        if (prow >= 0){
            #pragma unroll
            for (int i = 0; i < 18; i++) pv[i] += __shfl_xor_sync(FULL, pv[i], 16);
            #pragma unroll
            for (int i = 0; i < 18; i++) pv[i] += __shfl_xor_sync(FULL, pv[i], 8);
            if (lane < 8){
                float* dst = spart[pbuf][warp*8 + lane];
                *(float4*)(dst)      = make_float4(pv[0],  pv[1],  pv[2],  pv[3]);
                *(float4*)(dst + 4)  = make_float4(pv[4],  pv[5],  pv[6],  pv[7]);
                *(float4*)(dst + 8)  = make_float4(pv[8],  pv[9],  pv[10], pv[11]);
                *(float4*)(dst + 12) = make_float4(pv[12], pv[13], pv[14], pv[15]);
                *(float2*)(dst + 16) = make_float2(pv[16], pv[17]);
            }
            __syncthreads();
            if (warp == 0){            // tail for prow; warps 1-7 run ahead
                float t0 = 0.f, t1 = 0.f, t2 = 0.f, t3 = 0.f;
                #pragma unroll
                for (int j = 0; j < 64; j += 4){
                    t0 += spart[pbuf][j    ][lane];
                    t1 += spart[pbuf][j + 1][lane];
                    t2 += spart[pbuf][j + 2][lane];
                    t3 += spart[pbuf][j + 3][lane];
                }
                float t = (t0 + t1) + (t2 + t3);
                float s1 = __shfl_sync(FULL, t, 16);
                float s2 = __shfl_sync(FULL, t, 17);
                float mu  = s1 * (1.0f/DM);
                float var = s2 * (1.0f/DM) - mu*mu;
                float rs  = rsqrtf(var + 1e-5f);
                if (lane < 16){
                    g_u[prow*DS + lane] = fmaf(-mu, cBl, t) * rs + bBl;
                } else if (lane == 16){
                    g_murs[prow] = make_float2(mu, rs);
                }
            }
            pbuf ^= 1;
        }

        #pragma unroll
        for (int i = 0; i < 18; i++) pv[i] = p[i];
        prow = row;
    }

    // ---- flush last row ----
    {
        #pragma unroll
        for (int i = 0; i < 18; i++) pv[i] += __shfl_xor_sync(FULL, pv[i], 16);
        #pragma unroll
        for (int i = 0; i < 18; i++) pv[i] += __shfl_xor_sync(FULL, pv[i], 8);
        if (lane < 8){
            float* dst = spart[pbuf][warp*8 + lane];
            *(float4*)(dst)      = make_float4(pv[0],  pv[1],  pv[2],  pv[3]);
            *(float4*)(dst + 4)  = make_float4(pv[4],  pv[5],  pv[6],  pv[7]);
            *(float4*)(dst + 8)  = make_float4(pv[8],  pv[9],  pv[10], pv[11]);
            *(float4*)(dst + 12) = make_float4(pv[12], pv[13], pv[14], pv[15]);
            *(float2*)(dst + 16) = make_float2(pv[16], pv[17]);
        }
        __syncthreads();
        if (warp == 0){
            float t0 = 0.f, t1 = 0.f, t2 = 0.f, t3 = 0.f;
            #pragma unroll
            for (int j = 0; j < 64; j += 4){
                t0 += spart[pbuf][j    ][lane];
                t1 += spart[pbuf][j + 1][lane];
                t2 += spart[pbuf][j + 2][lane];
                t3 += spart[pbuf][j + 3][lane];
            }
            float t = (t0 + t1) + (t2 + t3);
            float s1 = __shfl_sync(FULL, t, 16);
            float s2 = __shfl_sync(FULL, t, 17);
            float mu  = s1 * (1.0f/DM);
            float var = s2 * (1.0f/DM) - mu*mu;
            float rs  = rsqrtf(var + 1e-5f);
            if (lane < 16){
                g_u[prow*DS + lane] = fmaf(-mu, cBl, t) * rs + bBl;
            } else if (lane == 16){
                g_murs[prow] = make_float2(mu, rs);
            }
        }
    }
}

// ---------------------------------------------------------------------------
// kernScan: chunked-parallel exact scan (unchanged).
// ---------------------------------------------------------------------------
__global__ __launch_bounds__(32, 1)
void kernScan(const float* __restrict__ A){
    const int chunk = blockIdx.x;
    const int b     = chunk / NCHUNK;
    const int c     = chunk % NCHUNK;
    const int t0    = c * CHL;
    const int start = (c == 0) ? 0 : (t0 - CHW);
    const int steps = t0 + CHL - start;
    const int lane  = threadIdx.x;

    float a[16];
    #pragma unroll
    for (int j = 0; j < 16; j++) a[j] = A[j*DS + (lane & 15)];

    const float* ub = g_u     + (size_t)b * SEQ * DS + (size_t)start * DS;
    float*       hb = g_hist2 + (size_t)(b * SEQ + start) * 32;

    __shared__ float sh[2][32];
    sh[0][lane] = 0.f;
    __syncthreads();

    float uq[4];
    #pragma unroll
    for (int k = 0; k < 4; k++) uq[k] = ub[k*DS + lane];

    const int body0 = t0 - start;
    for (int s = 0; s < steps; s += 4){
        #pragma unroll
        for (int k = 0; k < 4; k++){
            const int i = s + k;
            const int p = i & 1;
            float uc = uq[k];
            uq[k] = ub[(i + 4)*DS + lane];

            float4 H0 = *(const float4*)&sh[p][0];
            float4 H1 = *(const float4*)&sh[p][4];
            float4 H2 = *(const float4*)&sh[p][8];
            float4 H3 = *(const float4*)&sh[p][12];

            float a0 = fmaf(H0.x, a[0], uc);
            float a1 = H0.y * a[1];
            float a2 = H0.z * a[2];
            float a3 = H0.w * a[3];
            float a4 = H1.x * a[4];
            float a5 = H1.y * a[5];
            float a6 = H1.z * a[6];
            float a7 = H1.w * a[7];
            a0 = fmaf(H2.x, a[8],  a0);
            a1 = fmaf(H2.y, a[9],  a1);
            a2 = fmaf(H2.z, a[10], a2);
            a3 = fmaf(H2.w, a[11], a3);
            a4 = fmaf(H3.x, a[12], a4);
            a5 = fmaf(H3.y, a[13], a5);
            a6 = fmaf(H3.z, a[14], a6);
            a7 = fmaf(H3.w, a[15], a7);
            float v = ((a0 + a1) + (a2 + a3)) + ((a4 + a5) + (a6 + a7));
            float h = tanh_fast(v);

            sh[p ^ 1][lane] = h;
            __syncthreads();

            if (i >= body0) hb[i*32 + lane] = h;
        }
    }
}

// ---------------------------------------------------------------------------
// kernC: R8 shape (measured best): half-DM split, 2 blocks/SM, float4 I/O,
//        2-row pairwise unroll + 2-pair x prefetch.
// ---------------------------------------------------------------------------
__global__ __launch_bounds__(256, 2)
void kernC(const float* __restrict__ x,
           const float* __restrict__ Cm,
           const float* __restrict__ Dp,
           const float* __restrict__ gamma,
           const float* __restrict__ beta,
           float* __restrict__ out){
    const int tid  = threadIdx.x;
    const int half = blockIdx.x & 1;
    const int d0   = half * (DM/2) + tid * 4;

    float e[4], f[4];
    {
        float4 dp = *(const float4*)(Dp    + d0);
        float4 g  = *(const float4*)(gamma + d0);
        float4 btv= *(const float4*)(beta  + d0);
        float dv[4] = {dp.x,dp.y,dp.z,dp.w};
        float gv[4] = {g.x,g.y,g.z,g.w};
        float bv[4] = {btv.x,btv.y,btv.z,btv.w};
        #pragma unroll
        for (int k = 0; k < 4; k++){
            float cc = 1.0f + dv[k];
            e[k] = cc * gv[k];
            f[k] = cc * bv[k];
        }
    }
    float cr[16][4];
    #pragma unroll
    for (int s = 0; s < 16; s++){
        float4 c0 = *(const float4*)(Cm + s*DM + d0);
        cr[s][0]=c0.x; cr[s][1]=c0.y; cr[s][2]=c0.z; cr[s][3]=c0.w;
    }

    const int base = blockIdx.x >> 1;             // 0..147
    auto ldx = [&](int r){                        // clamp-indexed (branchless)
        int rc = r < NROWS ? r : NROWS-1;
        return *(const float4*)(x + (size_t)rc*DM + d0);
    };
    float4 x0 = ldx(base);
    float4 x1 = ldx(base + 148);
    float4 p0 = ldx(base + 296);
    float4 p1 = ldx(base + 444);

    for (int r = base; r < NROWS; r += 296){
        float4 c0 = x0, c1 = x1;
        x0 = p0; x1 = p1;
        p0 = ldx(r + 592);
        p1 = ldx(r + 740);

        int rB  = r + 148;
        int rBc = rB < NROWS ? rB : NROWS-1;

        float2 mrA = g_murs[r];
        float2 mrB = g_murs[rBc];
        const float4* hpA = (const float4*)(g_hist2 + (size_t)r*32);
        const float4* hpB = (const float4*)(g_hist2 + (size_t)rBc*32);
        float4 hA0 = hpA[0], hA1 = hpA[1], hA2 = hpA[2], hA3 = hpA[3];
        float4 hB0 = hpB[0], hB1 = hpB[1], hB2 = hpB[2], hB3 = hpB[3];
        float hvA[16] = {hA0.x,hA0.y,hA0.z,hA0.w, hA1.x,hA1.y,hA1.z,hA1.w,
                         hA2.x,hA2.y,hA2.z,hA2.w, hA3.x,hA3.y,hA3.z,hA3.w};
        float hvB[16] = {hB0.x,hB0.y,hB0.z,hB0.w, hB1.x,hB1.y,hB1.z,hB1.w,
                         hB2.x,hB2.y,hB2.z,hB2.w, hB3.x,hB3.y,hB3.z,hB3.w};

        float xsA[4] = {c0.x, c0.y, c0.z, c0.w};
        float xsB[4] = {c1.x, c1.y, c1.z, c1.w};
        float oA[4], oB[4];
        #pragma unroll
        for (int k = 0; k < 4; k++){
            float xcA = (xsA[k] - mrA.x) * mrA.y;
            float xcB = (xsB[k] - mrB.x) * mrB.y;
            float aA  = fmaf(e[k], xcA, f[k]);
            float aB  = fmaf(e[k], xcB, f[k]);
            #pragma unroll
            for (int s = 0; s < 16; s++){
                aA = fmaf(hvA[s], cr[s][k], aA);
                aB = fmaf(hvB[s], cr[s][k], aB);
            }
            oA[k] = aA; oB[k] = aB;
        }
        *(float4*)(out + (size_t)r*DM + d0) = make_float4(oA[0], oA[1], oA[2], oA[3]);
        if (rB < NROWS)
            *(float4*)(out + (size_t)rB*DM + d0) = make_float4(oB[0], oB[1], oB[2], oB[3]);
    }
}

// ---------------------------------------------------------------------------
extern "C" void kernel_launch(void* const* d_in, const int* in_sizes, int n_in,
                              void* d_out, int out_size){
    const float* x     = (const float*)d_in[0];
    const float* A     = (const float*)d_in[1];
    const float* B     = (const float*)d_in[2];
    const float* C     = (const float*)d_in[3];
    const float* Dp    = (const float*)d_in[4];
    const float* gamma = (const float*)d_in[5];
    const float* beta  = (const float*)d_in[6];
    float* out = (float*)d_out;

    kernA<<<148, 256>>>(x, B, gamma, beta);
    kernScan<<<NB*NCHUNK, 32>>>(A);
    kernC<<<296, 256>>>(x, C, Dp, gamma, beta, out);
}